// round 6
// baseline (speedup 1.0000x reference)
#include <cuda_runtime.h>
#include <cuda_bf16.h>
#include <cstdint>
#include <math.h>

using u32 = unsigned int;
using u64 = unsigned long long;

#define HEADS 12
#define DIM   64
#define BB    8
#define TT    1024
#define DIN   768
#define NPROJ 1536
#define NEGV  1000000000000.0f

// Scratch (no cudaMalloc allowed)
__device__ __nv_bfloat16 g_hs[BB*TT*DIN];        // hidden_states bf16 [m][k]
__device__ __nv_bfloat16 g_wT[NPROJ*DIN];        // W transposed bf16 [n][k]
__device__ __nv_bfloat16 g_q[BB*HEADS*TT*DIM];   // [bh][t][d]
__device__ __nv_bfloat16 g_k[BB*HEADS*TT*DIM];
__device__ float g_sin[32*TT];                   // transposed: [i][t]
__device__ float g_cos[32*TT];

// ---------------------------------------------------------------------------
// Helpers
// ---------------------------------------------------------------------------
__device__ __forceinline__ u32 smem_u32(const void* p) {
    u32 a;
    asm("{ .reg .u64 t; cvta.to.shared.u64 t, %1; cvt.u32.u64 %0, t; }"
        : "=r"(a) : "l"(p));
    return a;
}
__device__ __forceinline__ void cp_async16(u32 dst, const void* src) {
    asm volatile("cp.async.cg.shared.global [%0], [%1], 16;\n"
                 :: "r"(dst), "l"(src));
}
__device__ __forceinline__ void cp_commit() {
    asm volatile("cp.async.commit_group;\n" ::: "memory");
}
#define CP_WAIT(N) asm volatile("cp.async.wait_group %0;\n"::"n"(N):"memory")

__device__ __forceinline__ void ldsm_x4(u32 r[4], u32 addr) {
    asm volatile("ldmatrix.sync.aligned.m8n8.x4.shared.b16 {%0,%1,%2,%3}, [%4];"
        : "=r"(r[0]), "=r"(r[1]), "=r"(r[2]), "=r"(r[3]) : "r"(addr));
}
__device__ __forceinline__ void mma16816(float d[4], const u32 a[4],
                                         const u32 b0, const u32 b1) {
    asm volatile(
        "mma.sync.aligned.m16n8k16.row.col.f32.bf16.bf16.f32 "
        "{%0,%1,%2,%3}, {%4,%5,%6,%7}, {%8,%9}, {%0,%1,%2,%3};\n"
        : "+f"(d[0]), "+f"(d[1]), "+f"(d[2]), "+f"(d[3])
        : "r"(a[0]), "r"(a[1]), "r"(a[2]), "r"(a[3]), "r"(b0), "r"(b1));
}

// ---------------------------------------------------------------------------
// Kernel 0: RoPE table (transposed [i][t]).
// ---------------------------------------------------------------------------
__global__ void rope_table_kernel() {
    int id = blockIdx.x * blockDim.x + threadIdx.x;
    if (id >= TT * 32) return;
    int t = id >> 5;
    int i = id & 31;
    float invf = exp2f(-(float)i * 0.4152410118610286f);   // log2(1e4)/32
    float ang = (float)t * invf;
    float s, c;
    sincosf(ang, &s, &c);
    g_sin[i * TT + t] = s;
    g_cos[i * TT + t] = c;
}

// ---------------------------------------------------------------------------
// Kernel 1a/1b: fp32 -> bf16 conversions.
// ---------------------------------------------------------------------------
__global__ void conv_hs_kernel(const float* __restrict__ hs) {
    int f = blockIdx.x * blockDim.x + threadIdx.x;
    float4 v = reinterpret_cast<const float4*>(hs)[f];
    __nv_bfloat162 lo = __floats2bfloat162_rn(v.x, v.y);
    __nv_bfloat162 hi = __floats2bfloat162_rn(v.z, v.w);
    uint2 o;
    o.x = *reinterpret_cast<u32*>(&lo);
    o.y = *reinterpret_cast<u32*>(&hi);
    reinterpret_cast<uint2*>(g_hs)[f] = o;
}

__global__ void conv_w_kernel(const float* __restrict__ W) {
    __shared__ float tile[32][33];
    int n0 = blockIdx.x * 32, k0 = blockIdx.y * 32;
    int tx = threadIdx.x & 31, ty = threadIdx.x >> 5;
    #pragma unroll
    for (int r = ty; r < 32; r += 8)
        tile[r][tx] = W[(size_t)(k0 + r) * NPROJ + n0 + tx];
    __syncthreads();
    #pragma unroll
    for (int r = ty; r < 32; r += 8)
        g_wT[(size_t)(n0 + r) * DIN + k0 + tx] = __float2bfloat16(tile[tx][r]);
}

// ---------------------------------------------------------------------------
// Kernel 2: projection GEMM (M=8192,N=1536,K=768) — mma.sync + ldmatrix +
// cp.async double buffering. Block 128x128, BK=32, 8 warps (4m x 2n),
// warp tile 32x64. Epilogue: bias + RoPE -> g_q/g_k (bf16).
// Smem row stride: 40 bf16 = 80 B (16B-aligned, LDSM conflict-free).
// ---------------------------------------------------------------------------
__global__ void __launch_bounds__(256)
proj_rope_kernel(const float* __restrict__ bias) {
    __shared__ __nv_bfloat16 As[2][128 * 40];
    __shared__ __nv_bfloat16 Bs[2][128 * 40];

    const int tid  = threadIdx.x;
    const int m0   = blockIdx.y * 128;
    const int n0   = blockIdx.x * 128;
    const int warp = tid >> 5, lane = tid & 31;
    const int wm = warp >> 1, wn = warp & 1;
    const int g = lane >> 2, tig = lane & 3;

    const u32 aS[2] = { smem_u32(As[0]), smem_u32(As[1]) };
    const u32 bS[2] = { smem_u32(Bs[0]), smem_u32(Bs[1]) };

    // cp.async: 1024 16B chunks (A:512, B:512), 4 per thread.
    const int c_isA = tid < 128 ? 1 : 1;   // split by l below
    auto load_stage = [&](int k0c, int buf) {
        #pragma unroll
        for (int l = 0; l < 4; l++) {
            int c = tid + l * 256;          // 0..1023
            bool isA = c < 512;
            int cc  = c & 511;
            int row = cc >> 2;
            int kc  = (cc & 3) * 8;         // bf16 offset within 32
            const __nv_bfloat16* src =
                (isA ? g_hs + (size_t)(m0 + row) * DIN
                     : g_wT + (size_t)(n0 + row) * DIN) + k0c + kc;
            u32 dst = (isA ? aS[buf] : bS[buf]) + row * 80 + kc * 2;
            cp_async16(dst, src);
        }
        cp_commit();
    };
    (void)c_isA;

    float acc[2][8][4] = {};

    // LDSM lane addressing (byte offsets within a tile)
    const int a_row = (lane & 15);              // + wm*32 + mi*16
    const int a_kb  = (lane >> 4) * 16;         // k-half select
    const int b_row = ((lane >> 4) << 3) + (lane & 7);   // + wn*64 + np*16
    const int b_kb  = ((lane >> 3) & 1) * 16;

    load_stage(0, 0);

    int buf = 0;
    #pragma unroll 1
    for (int kt = 0; kt < 24; kt++) {
        if (kt < 23) load_stage((kt + 1) * 32, buf ^ 1);
        if (kt < 23) { CP_WAIT(1); } else { CP_WAIT(0); }
        __syncthreads();

        #pragma unroll
        for (int ks = 0; ks < 2; ks++) {        // two k16 steps
            u32 a[2][4];
            #pragma unroll
            for (int mi = 0; mi < 2; mi++) {
                int row = wm * 32 + mi * 16 + a_row;
                ldsm_x4(a[mi], aS[buf] + row * 80 + ks * 32 + a_kb);
            }
            #pragma unroll
            for (int np = 0; np < 4; np++) {
                int nrow = wn * 64 + np * 16 + b_row;
                u32 bfr[4];
                ldsm_x4(bfr, bS[buf] + nrow * 80 + ks * 32 + b_kb);
                mma16816(acc[0][np * 2 + 0], a[0], bfr[0], bfr[1]);
                mma16816(acc[1][np * 2 + 0], a[1], bfr[0], bfr[1]);
                mma16816(acc[0][np * 2 + 1], a[0], bfr[2], bfr[3]);
                mma16816(acc[1][np * 2 + 1], a[1], bfr[2], bfr[3]);
            }
        }
        __syncthreads();
        buf ^= 1;
    }

    // Epilogue: bias + RoPE, scatter bf16 pairs into g_q / g_k.
    #pragma unroll
    for (int ni = 0; ni < 8; ni++) {
        int n = n0 + wn * 64 + ni * 8 + 2 * tig;     // even column
        float b0v = __ldg(&bias[n]);
        float b1v = __ldg(&bias[n + 1]);
        int h = n >> 7, c = n & 127;
        bool isk = (c >= 64);
        int dd = isk ? c - 64 : c;
        int ip = dd >> 1;
        __nv_bfloat16* dst = isk ? g_k : g_q;
        #pragma unroll
        for (int mi = 0; mi < 2; mi++) {
            #pragma unroll
            for (int rs = 0; rs < 2; rs++) {
                int m = m0 + wm * 32 + mi * 16 + g + rs * 8;
                int t = m & (TT - 1);
                int batch = m >> 10;
                float s  = g_sin[ip * TT + t];
                float co = g_cos[ip * TT + t];
                float x0 = acc[mi][ni][rs * 2 + 0] + b0v;
                float x1 = acc[mi][ni][rs * 2 + 1] + b1v;
                size_t off =
                    ((size_t)((batch * HEADS + h) * TT + t)) * DIM + dd;
                *reinterpret_cast<__nv_bfloat162*>(&dst[off]) =
                    __floats2bfloat162_rn(x0 * co - x1 * s, x1 * co + x0 * s);
            }
        }
    }
}

// ---------------------------------------------------------------------------
// Kernel 3: logits — upper-triangular 128x128 tiles (36/bh), ldmatrix+mma.
// Smem row stride 72 bf16 = 144 B (16B-aligned, LDSM conflict-free).
// ---------------------------------------------------------------------------
__global__ void __launch_bounds__(256)
logits_kernel(const int* __restrict__ mask, float* __restrict__ out) {
    int idx = blockIdx.x;
    int tm = 0, rem = idx;
    while (rem >= 8 - tm) { rem -= 8 - tm; tm++; }
    const int tile_m = tm, tile_n = tm + rem;

    const int bh  = blockIdx.y;
    const int b   = bh / HEADS;
    const int tid = threadIdx.x;
    const size_t outbase = (size_t)bh * TT * TT;

    __shared__ __nv_bfloat16 Qs[128 * 72];
    __shared__ __nv_bfloat16 Ks[128 * 72];
    __shared__ float mvs[128];
    const u32 qS = smem_u32(Qs);
    const u32 kS = smem_u32(Ks);

    const __nv_bfloat16* qptr = g_q + (size_t)bh * TT * DIM +
                                (size_t)tile_m * 128 * DIM;
    const __nv_bfloat16* kptr = g_k + (size_t)bh * TT * DIM +
                                (size_t)tile_n * 128 * DIM;

    if (tid < 128) mvs[tid] = (float)mask[b * TT + tile_n * 128 + tid];

    #pragma unroll
    for (int l = 0; l < 4; l++) {
        int f   = tid + l * 256;
        int row = f >> 3;
        int qo  = (f & 7) * 8;
        *reinterpret_cast<uint4*>(&Qs[row * 72 + qo]) =
            *reinterpret_cast<const uint4*>(&qptr[row * DIM + qo]);
        *reinterpret_cast<uint4*>(&Ks[row * 72 + qo]) =
            *reinterpret_cast<const uint4*>(&kptr[row * DIM + qo]);
    }
    __syncthreads();

    const int warp = tid >> 5, lane = tid & 31;
    const int wm = warp >> 1, wn = warp & 1;
    const int g = lane >> 2, tig = lane & 3;

    const int a_row = (lane & 15);
    const int a_kb  = (lane >> 4) * 16;
    const int b_row = ((lane >> 4) << 3) + (lane & 7);
    const int b_kb  = ((lane >> 3) & 1) * 16;

    float acc[2][8][4] = {};
    #pragma unroll
    for (int ks = 0; ks < 4; ks++) {            // k = 0,16,32,48
        u32 a[2][4];
        #pragma unroll
        for (int mi = 0; mi < 2; mi++) {
            int row = wm * 32 + mi * 16 + a_row;
            ldsm_x4(a[mi], qS + row * 144 + ks * 32 + a_kb);
        }
        #pragma unroll
        for (int np = 0; np < 4; np++) {
            int nrow = wn * 64 + np * 16 + b_row;
            u32 bfr[4];
            ldsm_x4(bfr, kS + nrow * 144 + ks * 32 + b_kb);
            mma16816(acc[0][np * 2 + 0], a[0], bfr[0], bfr[1]);
            mma16816(acc[1][np * 2 + 0], a[1], bfr[0], bfr[1]);
            mma16816(acc[0][np * 2 + 1], a[0], bfr[2], bfr[3]);
            mma16816(acc[1][np * 2 + 1], a[1], bfr[2], bfr[3]);
        }
    }

    const int nl = wn * 64 + 2 * tig;
    float mv0[8], mv1[8];
    #pragma unroll
    for (int ni = 0; ni < 8; ni++) {
        mv0[ni] = mvs[nl + ni * 8];
        mv1[ni] = mvs[nl + ni * 8 + 1];
    }
    #pragma unroll
    for (int mi = 0; mi < 2; mi++) {
        #pragma unroll
        for (int rs = 0; rs < 2; rs++) {
            int m = tile_m * 128 + wm * 32 + mi * 16 + g + rs * 8;
            size_t rowoff = outbase + (size_t)m * TT;
            #pragma unroll
            for (int ni = 0; ni < 8; ni++) {
                int n = tile_n * 128 + nl + ni * 8;
                float v0 = acc[mi][ni][rs * 2 + 0] * mv0[ni]
                           - (1.0f - mv0[ni]) * NEGV;
                float v1 = acc[mi][ni][rs * 2 + 1] * mv1[ni]
                           - (1.0f - mv1[ni]) * NEGV;
                if (n < m)     v0 -= NEGV;
                if (n + 1 < m) v1 -= NEGV;
                *reinterpret_cast<float2*>(&out[rowoff + n]) =
                    make_float2(v0 * 0.125f, v1 * 0.125f);
            }
        }
    }
}

// ---------------------------------------------------------------------------
// Kernel 4: strict-lower fill.
// ---------------------------------------------------------------------------
__global__ void __launch_bounds__(256)
fill_kernel(const int* __restrict__ mask, float* __restrict__ out) {
    int idx = blockIdx.x;
    int tm = 1, rem = idx;
    while (rem >= tm) { rem -= tm; tm++; }
    const int tile_m = tm, tile_n = rem;

    const int bh  = blockIdx.y;
    const int b   = bh / HEADS;
    const int tid = threadIdx.x;
    const size_t outbase = (size_t)bh * TT * TT;

    __shared__ float colval[128];
    if (tid < 128) {
        float mv = (float)mask[b * TT + tile_n * 128 + tid];
        colval[tid] = (-(1.0f - mv) * NEGV - NEGV) * 0.125f;
    }
    __syncthreads();

    #pragma unroll
    for (int l = 0; l < 16; l++) {
        int f   = tid + l * 256;
        int row = f >> 5;
        int c4  = (f & 31) * 4;
        float4 v = *reinterpret_cast<const float4*>(&colval[c4]);
        int m = tile_m * 128 + row;
        int n = tile_n * 128 + c4;
        *reinterpret_cast<float4*>(&out[outbase + (size_t)m * TT + n]) = v;
    }
}

// ---------------------------------------------------------------------------
extern "C" void kernel_launch(void* const* d_in, const int* in_sizes, int n_in,
                              void* d_out, int out_size) {
    const float* hs   = (const float*)d_in[0];
    const int*   mask = (const int*)  d_in[1];
    const float* W    = (const float*)d_in[2];
    const float* bias = (const float*)d_in[3];
    float* out = (float*)d_out;

    rope_table_kernel<<<128, 256>>>();
    conv_hs_kernel<<<(BB*TT*DIN/4 + 255)/256, 256>>>(hs);
    conv_w_kernel<<<dim3(NPROJ/32, DIN/32), 256>>>(W);

    dim3 gA(NPROJ / 128, (BB * TT) / 128);   // (12, 64)
    proj_rope_kernel<<<gA, 256>>>(bias);

    dim3 gB(36, BB * HEADS);                 // upper tiles
    logits_kernel<<<gB, 256>>>(mask, out);

    dim3 gC(28, BB * HEADS);                 // strict-lower tiles
    fill_kernel<<<gC, 256>>>(mask, out);
}

// round 7
// speedup vs baseline: 1.4467x; 1.4467x over previous
#include <cuda_runtime.h>
#include <cuda_bf16.h>
#include <cstdint>
#include <math.h>

using u32 = unsigned int;

#define HEADS 12
#define DIM   64
#define BB    8
#define TT    1024
#define DIN   768
#define NPROJ 1536
#define NEGV  1000000000000.0f

// Scratch (no cudaMalloc allowed)
__device__ __nv_bfloat16 g_hs[BB*TT*DIN];        // hidden_states bf16 [m][k]
__device__ __nv_bfloat16 g_wT[NPROJ*DIN];        // W transposed bf16 [n][k]
__device__ __nv_bfloat16 g_q[BB*HEADS*TT*DIM];   // [bh][t][d]
__device__ __nv_bfloat16 g_k[BB*HEADS*TT*DIM];
__device__ float g_sin[32*TT];                   // transposed: [i][t]
__device__ float g_cos[32*TT];

// ---------------------------------------------------------------------------
__device__ __forceinline__ u32 smem_u32(const void* p) {
    u32 a;
    asm("{ .reg .u64 t; cvta.to.shared.u64 t, %1; cvt.u32.u64 %0, t; }"
        : "=r"(a) : "l"(p));
    return a;
}
__device__ __forceinline__ void cp_async16(u32 dst, const void* src) {
    asm volatile("cp.async.cg.shared.global [%0], [%1], 16;\n"
                 :: "r"(dst), "l"(src));
}
__device__ __forceinline__ void cp_commit() {
    asm volatile("cp.async.commit_group;\n" ::: "memory");
}
#define CP_WAIT(N) asm volatile("cp.async.wait_group %0;\n"::"n"(N):"memory")

__device__ __forceinline__ void mma16816(float d[4], const u32 a[4],
                                         const u32 b0, const u32 b1) {
    asm volatile(
        "mma.sync.aligned.m16n8k16.row.col.f32.bf16.bf16.f32 "
        "{%0,%1,%2,%3}, {%4,%5,%6,%7}, {%8,%9}, {%0,%1,%2,%3};\n"
        : "+f"(d[0]), "+f"(d[1]), "+f"(d[2]), "+f"(d[3])
        : "r"(a[0]), "r"(a[1]), "r"(a[2]), "r"(a[3]), "r"(b0), "r"(b1));
}

// ---------------------------------------------------------------------------
// Kernel 0: RoPE table (transposed [i][t]).
// ---------------------------------------------------------------------------
__global__ void rope_table_kernel() {
    int id = blockIdx.x * blockDim.x + threadIdx.x;
    if (id >= TT * 32) return;
    int t = id >> 5;
    int i = id & 31;
    float invf = exp2f(-(float)i * 0.4152410118610286f);   // log2(1e4)/32
    float ang = (float)t * invf;
    float s, c;
    sincosf(ang, &s, &c);
    g_sin[i * TT + t] = s;
    g_cos[i * TT + t] = c;
}

// ---------------------------------------------------------------------------
// Kernel 1a/1b: fp32 -> bf16 conversions.
// ---------------------------------------------------------------------------
__global__ void conv_hs_kernel(const float* __restrict__ hs) {
    int f = blockIdx.x * blockDim.x + threadIdx.x;
    float4 v = reinterpret_cast<const float4*>(hs)[f];
    __nv_bfloat162 lo = __floats2bfloat162_rn(v.x, v.y);
    __nv_bfloat162 hi = __floats2bfloat162_rn(v.z, v.w);
    uint2 o;
    o.x = *reinterpret_cast<u32*>(&lo);
    o.y = *reinterpret_cast<u32*>(&hi);
    reinterpret_cast<uint2*>(g_hs)[f] = o;
}

__global__ void conv_w_kernel(const float* __restrict__ W) {
    __shared__ float tile[32][33];
    int n0 = blockIdx.x * 32, k0 = blockIdx.y * 32;
    int tx = threadIdx.x & 31, ty = threadIdx.x >> 5;
    #pragma unroll
    for (int r = ty; r < 32; r += 8)
        tile[r][tx] = W[(size_t)(k0 + r) * NPROJ + n0 + tx];
    __syncthreads();
    #pragma unroll
    for (int r = ty; r < 32; r += 8)
        g_wT[(size_t)(n0 + r) * DIN + k0 + tx] = __float2bfloat16(tile[tx][r]);
}

// ---------------------------------------------------------------------------
// Kernel 2: projection GEMM (M=8192,N=1536,K=768).
// Block 128x128, BK=32, 8 warps (4m x 2n), warp 32x64, scalar-LDS fragments
// (R3 compute), 4-stage cp.async pipeline (one commit group per stage).
// Stage layout in dynamic smem: A[128x40bf16] then B[128x40bf16] per stage.
// Epilogue: bias + RoPE -> g_q/g_k (bf16).
// ---------------------------------------------------------------------------
#define STAGE_BYTES (2 * 128 * 40 * 2)   // A + B, 20480 B
#define NSTAGE 4

__global__ void __launch_bounds__(256)
proj_rope_kernel(const float* __restrict__ bias) {
    extern __shared__ char dsm[];
    const u32 sb = smem_u32(dsm);

    const int tid  = threadIdx.x;
    const int m0   = blockIdx.y * 128;
    const int n0   = blockIdx.x * 128;
    const int warp = tid >> 5, lane = tid & 31;
    const int wm = warp >> 1, wn = warp & 1;
    const int g = lane >> 2, tig = lane & 3;

    // cp.async addressing: per thread 2 A-chunks + 2 B-chunks of 16B.
    const int r_row = tid >> 2;            // 0..63 (+64)
    const int r_kc  = (tid & 3) * 8;       // bf16 offset in 32-wide k chunk

    auto load_stage = [&](int k0c, int s) {
        u32 abase = sb + s * STAGE_BYTES;
        u32 bbase = abase + 128 * 80;
        #pragma unroll
        for (int l = 0; l < 2; l++) {
            int row = r_row + l * 64;
            cp_async16(abase + row * 80 + r_kc * 2,
                       g_hs + (size_t)(m0 + row) * DIN + k0c + r_kc);
            cp_async16(bbase + row * 80 + r_kc * 2,
                       g_wT + (size_t)(n0 + row) * DIN + k0c + r_kc);
        }
        cp_commit();
    };

    float acc[2][8][4] = {};

    // Prologue: 3 stages in flight.
    load_stage(0, 0);
    load_stage(32, 1);
    load_stage(64, 2);

    #pragma unroll 1
    for (int kt = 0; kt < 24; kt++) {
        CP_WAIT(2);            // stage kt complete (pending: kt+1, kt+2)
        __syncthreads();       // visibility + WAR for the buffer we refill
        if (kt + 3 < 24) load_stage((kt + 3) * 32, (kt + 3) & 3);
        else             cp_commit();   // keep group-count invariant

        const int s = kt & 3;
        const u32* As32 = reinterpret_cast<const u32*>(dsm + s * STAGE_BYTES);
        const u32* Bs32 = As32 + (128 * 80 / 4);

        #pragma unroll
        for (int ks2 = 0; ks2 < 16; ks2 += 8) {     // two k16 steps
            u32 a[2][4];
            #pragma unroll
            for (int mi = 0; mi < 2; mi++) {
                int r0 = wm * 32 + mi * 16 + g;
                a[mi][0] = As32[r0 * 20 + ks2 + tig];
                a[mi][1] = As32[(r0 + 8) * 20 + ks2 + tig];
                a[mi][2] = As32[r0 * 20 + ks2 + tig + 4];
                a[mi][3] = As32[(r0 + 8) * 20 + ks2 + tig + 4];
            }
            #pragma unroll
            for (int ni = 0; ni < 8; ni++) {
                int n = wn * 64 + ni * 8 + g;
                u32 b0 = Bs32[n * 20 + ks2 + tig];
                u32 b1 = Bs32[n * 20 + ks2 + tig + 4];
                mma16816(acc[0][ni], a[0], b0, b1);
                mma16816(acc[1][ni], a[1], b0, b1);
            }
        }
    }

    // Epilogue: bias + RoPE, scatter bf16 pairs into g_q / g_k.
    #pragma unroll
    for (int ni = 0; ni < 8; ni++) {
        int n = n0 + wn * 64 + ni * 8 + 2 * tig;     // even column
        float b0v = __ldg(&bias[n]);
        float b1v = __ldg(&bias[n + 1]);
        int h = n >> 7, c = n & 127;
        bool isk = (c >= 64);
        int dd = isk ? c - 64 : c;
        int ip = dd >> 1;
        __nv_bfloat16* dst = isk ? g_k : g_q;
        #pragma unroll
        for (int mi = 0; mi < 2; mi++) {
            #pragma unroll
            for (int rs = 0; rs < 2; rs++) {
                int m = m0 + wm * 32 + mi * 16 + g + rs * 8;
                int t = m & (TT - 1);
                int batch = m >> 10;
                float s  = g_sin[ip * TT + t];
                float co = g_cos[ip * TT + t];
                float x0 = acc[mi][ni][rs * 2 + 0] + b0v;
                float x1 = acc[mi][ni][rs * 2 + 1] + b1v;
                size_t off =
                    ((size_t)((batch * HEADS + h) * TT + t)) * DIM + dd;
                *reinterpret_cast<__nv_bfloat162*>(&dst[off]) =
                    __floats2bfloat162_rn(x0 * co - x1 * s, x1 * co + x0 * s);
            }
        }
    }
}

// ---------------------------------------------------------------------------
// Kernel 3: logits — upper-triangular 128x128 tiles (36/bh). R3 form.
// ---------------------------------------------------------------------------
__global__ void __launch_bounds__(256)
logits_kernel(const int* __restrict__ mask, float* __restrict__ out) {
    int idx = blockIdx.x;
    int tm = 0, rem = idx;
    while (rem >= 8 - tm) { rem -= 8 - tm; tm++; }
    const int tile_m = tm, tile_n = tm + rem;

    const int bh  = blockIdx.y;
    const int b   = bh / HEADS;
    const int tid = threadIdx.x;
    const size_t outbase = (size_t)bh * TT * TT;

    __shared__ __nv_bfloat16 Qs[128 * 72];
    __shared__ __nv_bfloat16 Ks[128 * 72];
    __shared__ float mvs[128];
    u32* Qs32 = reinterpret_cast<u32*>(Qs);
    u32* Ks32 = reinterpret_cast<u32*>(Ks);

    const __nv_bfloat16* qptr = g_q + (size_t)bh * TT * DIM +
                                (size_t)tile_m * 128 * DIM;
    const __nv_bfloat16* kptr = g_k + (size_t)bh * TT * DIM +
                                (size_t)tile_n * 128 * DIM;

    if (tid < 128) mvs[tid] = (float)mask[b * TT + tile_n * 128 + tid];

    #pragma unroll
    for (int l = 0; l < 4; l++) {
        int f   = tid + l * 256;
        int row = f >> 3;
        int qo  = (f & 7) * 8;
        *reinterpret_cast<uint4*>(&Qs[row * 72 + qo]) =
            *reinterpret_cast<const uint4*>(&qptr[row * DIM + qo]);
        *reinterpret_cast<uint4*>(&Ks[row * 72 + qo]) =
            *reinterpret_cast<const uint4*>(&kptr[row * DIM + qo]);
    }
    __syncthreads();

    const int warp = tid >> 5, lane = tid & 31;
    const int wm = warp >> 1, wn = warp & 1;
    const int g = lane >> 2, tig = lane & 3;

    float acc[2][8][4] = {};
    #pragma unroll
    for (int ks2 = 0; ks2 < 32; ks2 += 8) {
        u32 a[2][4];
        #pragma unroll
        for (int mi = 0; mi < 2; mi++) {
            int r0 = wm * 32 + mi * 16 + g;
            a[mi][0] = Qs32[r0 * 36 + ks2 + tig];
            a[mi][1] = Qs32[(r0 + 8) * 36 + ks2 + tig];
            a[mi][2] = Qs32[r0 * 36 + ks2 + tig + 4];
            a[mi][3] = Qs32[(r0 + 8) * 36 + ks2 + tig + 4];
        }
        #pragma unroll
        for (int ni = 0; ni < 8; ni++) {
            int n = wn * 64 + ni * 8 + g;
            u32 b0 = Ks32[n * 36 + ks2 + tig];
            u32 b1 = Ks32[n * 36 + ks2 + tig + 4];
            mma16816(acc[0][ni], a[0], b0, b1);
            mma16816(acc[1][ni], a[1], b0, b1);
        }
    }

    const int nl = wn * 64 + 2 * tig;
    float mv0[8], mv1[8];
    #pragma unroll
    for (int ni = 0; ni < 8; ni++) {
        mv0[ni] = mvs[nl + ni * 8];
        mv1[ni] = mvs[nl + ni * 8 + 1];
    }
    #pragma unroll
    for (int mi = 0; mi < 2; mi++) {
        #pragma unroll
        for (int rs = 0; rs < 2; rs++) {
            int m = tile_m * 128 + wm * 32 + mi * 16 + g + rs * 8;
            size_t rowoff = outbase + (size_t)m * TT;
            #pragma unroll
            for (int ni = 0; ni < 8; ni++) {
                int n = tile_n * 128 + nl + ni * 8;
                float v0 = acc[mi][ni][rs * 2 + 0] * mv0[ni]
                           - (1.0f - mv0[ni]) * NEGV;
                float v1 = acc[mi][ni][rs * 2 + 1] * mv1[ni]
                           - (1.0f - mv1[ni]) * NEGV;
                if (n < m)     v0 -= NEGV;
                if (n + 1 < m) v1 -= NEGV;
                *reinterpret_cast<float2*>(&out[rowoff + n]) =
                    make_float2(v0 * 0.125f, v1 * 0.125f);
            }
        }
    }
}

// ---------------------------------------------------------------------------
// Kernel 4: strict-lower fill.
// ---------------------------------------------------------------------------
__global__ void __launch_bounds__(256)
fill_kernel(const int* __restrict__ mask, float* __restrict__ out) {
    int idx = blockIdx.x;
    int tm = 1, rem = idx;
    while (rem >= tm) { rem -= tm; tm++; }
    const int tile_m = tm, tile_n = rem;

    const int bh  = blockIdx.y;
    const int b   = bh / HEADS;
    const int tid = threadIdx.x;
    const size_t outbase = (size_t)bh * TT * TT;

    __shared__ float colval[128];
    if (tid < 128) {
        float mv = (float)mask[b * TT + tile_n * 128 + tid];
        colval[tid] = (-(1.0f - mv) * NEGV - NEGV) * 0.125f;
    }
    __syncthreads();

    #pragma unroll
    for (int l = 0; l < 16; l++) {
        int f   = tid + l * 256;
        int row = f >> 5;
        int c4  = (f & 31) * 4;
        float4 v = *reinterpret_cast<const float4*>(&colval[c4]);
        int m = tile_m * 128 + row;
        int n = tile_n * 128 + c4;
        *reinterpret_cast<float4*>(&out[outbase + (size_t)m * TT + n]) = v;
    }
}

// ---------------------------------------------------------------------------
extern "C" void kernel_launch(void* const* d_in, const int* in_sizes, int n_in,
                              void* d_out, int out_size) {
    const float* hs   = (const float*)d_in[0];
    const int*   mask = (const int*)  d_in[1];
    const float* W    = (const float*)d_in[2];
    const float* bias = (const float*)d_in[3];
    float* out = (float*)d_out;

    const int proj_smem = NSTAGE * STAGE_BYTES;   // 81920
    cudaFuncSetAttribute(proj_rope_kernel,
                         cudaFuncAttributeMaxDynamicSharedMemorySize, proj_smem);

    rope_table_kernel<<<128, 256>>>();
    conv_hs_kernel<<<(BB*TT*DIN/4 + 255)/256, 256>>>(hs);
    conv_w_kernel<<<dim3(NPROJ/32, DIN/32), 256>>>(W);

    dim3 gA(NPROJ / 128, (BB * TT) / 128);   // (12, 64)
    proj_rope_kernel<<<gA, 256, proj_smem>>>(bias);

    dim3 gB(36, BB * HEADS);                 // upper tiles
    logits_kernel<<<gB, 256>>>(mask, out);

    dim3 gC(28, BB * HEADS);                 // strict-lower tiles
    fill_kernel<<<gC, 256>>>(mask, out);
}

// round 8
// speedup vs baseline: 1.4911x; 1.0307x over previous
#include <cuda_runtime.h>
#include <cuda_bf16.h>
#include <cstdint>
#include <math.h>

using u32 = unsigned int;

#define HEADS 12
#define DIM   64
#define BB    8
#define TT    1024
#define DIN   768
#define NPROJ 1536
#define NEGV  1000000000000.0f

// Scratch (no cudaMalloc allowed)
__device__ __nv_bfloat16 g_hs[BB*TT*DIN];        // hidden_states bf16 [m][k]
__device__ __nv_bfloat16 g_wT[NPROJ*DIN];        // W transposed bf16 [n][k]
__device__ __nv_bfloat16 g_q[BB*HEADS*TT*DIM];   // [bh][t][d]
__device__ __nv_bfloat16 g_k[BB*HEADS*TT*DIM];
__device__ float g_sin[32*TT];                   // transposed: [i][t]
__device__ float g_cos[32*TT];

// ---------------------------------------------------------------------------
__device__ __forceinline__ u32 smem_u32(const void* p) {
    u32 a;
    asm("{ .reg .u64 t; cvta.to.shared.u64 t, %1; cvt.u32.u64 %0, t; }"
        : "=r"(a) : "l"(p));
    return a;
}
__device__ __forceinline__ void cp_async16(u32 dst, const void* src) {
    asm volatile("cp.async.cg.shared.global [%0], [%1], 16;\n"
                 :: "r"(dst), "l"(src));
}
__device__ __forceinline__ void cp_commit() {
    asm volatile("cp.async.commit_group;\n" ::: "memory");
}
#define CP_WAIT(N) asm volatile("cp.async.wait_group %0;\n"::"n"(N):"memory")

__device__ __forceinline__ void mma16816(float d[4], const u32 a[4],
                                         const u32 b0, const u32 b1) {
    asm volatile(
        "mma.sync.aligned.m16n8k16.row.col.f32.bf16.bf16.f32 "
        "{%0,%1,%2,%3}, {%4,%5,%6,%7}, {%8,%9}, {%0,%1,%2,%3};\n"
        : "+f"(d[0]), "+f"(d[1]), "+f"(d[2]), "+f"(d[3])
        : "r"(a[0]), "r"(a[1]), "r"(a[2]), "r"(a[3]), "r"(b0), "r"(b1));
}

// ---------------------------------------------------------------------------
// Kernel 0: fused prep — conv_hs (blocks [0,6144)), conv_w [6144,7296),
// rope table [7296,7424). All independent elementwise/transpose work.
// ---------------------------------------------------------------------------
#define HS_BLOCKS   6144    // (BB*TT*DIN/4)/256
#define W_BLOCKS    1152    // (NPROJ/32)*(DIN/32)
#define ROPE_BLOCKS 128     // 32768/256

__global__ void __launch_bounds__(256)
prep_kernel(const float* __restrict__ hs, const float* __restrict__ W) {
    __shared__ float tile[32][33];
    const int blk = blockIdx.x;
    const int tid = threadIdx.x;

    if (blk < HS_BLOCKS) {
        int f = blk * 256 + tid;
        float4 v = reinterpret_cast<const float4*>(hs)[f];
        __nv_bfloat162 lo = __floats2bfloat162_rn(v.x, v.y);
        __nv_bfloat162 hi = __floats2bfloat162_rn(v.z, v.w);
        uint2 o;
        o.x = *reinterpret_cast<u32*>(&lo);
        o.y = *reinterpret_cast<u32*>(&hi);
        reinterpret_cast<uint2*>(g_hs)[f] = o;
    } else if (blk < HS_BLOCKS + W_BLOCKS) {
        int idx = blk - HS_BLOCKS;
        int n0 = (idx % 48) * 32, k0 = (idx / 48) * 32;
        int tx = tid & 31, ty = tid >> 5;
        #pragma unroll
        for (int r = ty; r < 32; r += 8)
            tile[r][tx] = W[(size_t)(k0 + r) * NPROJ + n0 + tx];
        __syncthreads();
        #pragma unroll
        for (int r = ty; r < 32; r += 8)
            g_wT[(size_t)(n0 + r) * DIN + k0 + tx] =
                __float2bfloat16(tile[tx][r]);
    } else {
        int id = (blk - HS_BLOCKS - W_BLOCKS) * 256 + tid;
        int t = id >> 5;
        int i = id & 31;
        float invf = exp2f(-(float)i * 0.4152410118610286f); // log2(1e4)/32
        float ang = (float)t * invf;
        float s, c;
        sincosf(ang, &s, &c);
        g_sin[i * TT + t] = s;
        g_cos[i * TT + t] = c;
    }
}

// ---------------------------------------------------------------------------
// Kernel 1: projection GEMM (M=8192,N=1536,K=768).
// Block 128x128, BK=32, 512 threads = 16 warps (4m x 4n), warp tile 32x32.
// Scalar-LDS fragments, 4-stage cp.async pipeline.
// Epilogue: bias + RoPE -> g_q/g_k (bf16).
// ---------------------------------------------------------------------------
#define STAGE_BYTES (2 * 128 * 40 * 2)   // A + B, 20480 B
#define NSTAGE 4

__global__ void __launch_bounds__(512, 2)
proj_rope_kernel(const float* __restrict__ bias) {
    extern __shared__ char dsm[];
    const u32 sb = smem_u32(dsm);

    const int tid  = threadIdx.x;
    const int m0   = blockIdx.y * 128;
    const int n0   = blockIdx.x * 128;
    const int warp = tid >> 5, lane = tid & 31;
    const int wm = warp >> 2, wn = warp & 3;
    const int g = lane >> 2, tig = lane & 3;

    // cp.async: 512 A-chunks + 512 B-chunks of 16B per stage; 1 each/thread.
    const int r_row = tid >> 2;            // 0..127
    const int r_kc  = (tid & 3) * 8;       // bf16 offset in 32-wide k chunk

    auto load_stage = [&](int k0c, int s) {
        u32 abase = sb + s * STAGE_BYTES;
        u32 bbase = abase + 128 * 80;
        cp_async16(abase + r_row * 80 + r_kc * 2,
                   g_hs + (size_t)(m0 + r_row) * DIN + k0c + r_kc);
        cp_async16(bbase + r_row * 80 + r_kc * 2,
                   g_wT + (size_t)(n0 + r_row) * DIN + k0c + r_kc);
        cp_commit();
    };

    float acc[2][4][4] = {};

    // Prologue: 3 stages in flight.
    load_stage(0, 0);
    load_stage(32, 1);
    load_stage(64, 2);

    #pragma unroll 1
    for (int kt = 0; kt < 24; kt++) {
        CP_WAIT(2);            // stage kt complete (pending: kt+1, kt+2)
        __syncthreads();       // visibility + WAR for the buffer we refill
        if (kt + 3 < 24) load_stage((kt + 3) * 32, (kt + 3) & 3);
        else             cp_commit();   // keep group-count invariant

        const int s = kt & 3;
        const u32* As32 = reinterpret_cast<const u32*>(dsm + s * STAGE_BYTES);
        const u32* Bs32 = As32 + (128 * 80 / 4);

        #pragma unroll
        for (int ks2 = 0; ks2 < 16; ks2 += 8) {     // two k16 steps
            u32 a[2][4];
            #pragma unroll
            for (int mi = 0; mi < 2; mi++) {
                int r0 = wm * 32 + mi * 16 + g;
                a[mi][0] = As32[r0 * 20 + ks2 + tig];
                a[mi][1] = As32[(r0 + 8) * 20 + ks2 + tig];
                a[mi][2] = As32[r0 * 20 + ks2 + tig + 4];
                a[mi][3] = As32[(r0 + 8) * 20 + ks2 + tig + 4];
            }
            #pragma unroll
            for (int ni = 0; ni < 4; ni++) {
                int n = wn * 32 + ni * 8 + g;
                u32 b0 = Bs32[n * 20 + ks2 + tig];
                u32 b1 = Bs32[n * 20 + ks2 + tig + 4];
                mma16816(acc[0][ni], a[0], b0, b1);
                mma16816(acc[1][ni], a[1], b0, b1);
            }
        }
    }

    // Epilogue: bias + RoPE, scatter bf16 pairs into g_q / g_k.
    #pragma unroll
    for (int ni = 0; ni < 4; ni++) {
        int n = n0 + wn * 32 + ni * 8 + 2 * tig;     // even column
        float b0v = __ldg(&bias[n]);
        float b1v = __ldg(&bias[n + 1]);
        int h = n >> 7, c = n & 127;
        bool isk = (c >= 64);
        int dd = isk ? c - 64 : c;
        int ip = dd >> 1;
        __nv_bfloat16* dst = isk ? g_k : g_q;
        #pragma unroll
        for (int mi = 0; mi < 2; mi++) {
            #pragma unroll
            for (int rs = 0; rs < 2; rs++) {
                int m = m0 + wm * 32 + mi * 16 + g + rs * 8;
                int t = m & (TT - 1);
                int batch = m >> 10;
                float s  = g_sin[ip * TT + t];
                float co = g_cos[ip * TT + t];
                float x0 = acc[mi][ni][rs * 2 + 0] + b0v;
                float x1 = acc[mi][ni][rs * 2 + 1] + b1v;
                size_t off =
                    ((size_t)((batch * HEADS + h) * TT + t)) * DIM + dd;
                *reinterpret_cast<__nv_bfloat162*>(&dst[off]) =
                    __floats2bfloat162_rn(x0 * co - x1 * s, x1 * co + x0 * s);
            }
        }
    }
}

// ---------------------------------------------------------------------------
// Kernel 2: logits — upper-triangular 128x128 tiles (36/bh). R3 form.
// ---------------------------------------------------------------------------
__global__ void __launch_bounds__(256)
logits_kernel(const int* __restrict__ mask, float* __restrict__ out) {
    int idx = blockIdx.x;
    int tm = 0, rem = idx;
    while (rem >= 8 - tm) { rem -= 8 - tm; tm++; }
    const int tile_m = tm, tile_n = tm + rem;

    const int bh  = blockIdx.y;
    const int b   = bh / HEADS;
    const int tid = threadIdx.x;
    const size_t outbase = (size_t)bh * TT * TT;

    __shared__ __nv_bfloat16 Qs[128 * 72];
    __shared__ __nv_bfloat16 Ks[128 * 72];
    __shared__ float mvs[128];
    u32* Qs32 = reinterpret_cast<u32*>(Qs);
    u32* Ks32 = reinterpret_cast<u32*>(Ks);

    const __nv_bfloat16* qptr = g_q + (size_t)bh * TT * DIM +
                                (size_t)tile_m * 128 * DIM;
    const __nv_bfloat16* kptr = g_k + (size_t)bh * TT * DIM +
                                (size_t)tile_n * 128 * DIM;

    if (tid < 128) mvs[tid] = (float)mask[b * TT + tile_n * 128 + tid];

    #pragma unroll
    for (int l = 0; l < 4; l++) {
        int f   = tid + l * 256;
        int row = f >> 3;
        int qo  = (f & 7) * 8;
        *reinterpret_cast<uint4*>(&Qs[row * 72 + qo]) =
            *reinterpret_cast<const uint4*>(&qptr[row * DIM + qo]);
        *reinterpret_cast<uint4*>(&Ks[row * 72 + qo]) =
            *reinterpret_cast<const uint4*>(&kptr[row * DIM + qo]);
    }
    __syncthreads();

    const int warp = tid >> 5, lane = tid & 31;
    const int wm = warp >> 1, wn = warp & 1;
    const int g = lane >> 2, tig = lane & 3;

    float acc[2][8][4] = {};
    #pragma unroll
    for (int ks2 = 0; ks2 < 32; ks2 += 8) {
        u32 a[2][4];
        #pragma unroll
        for (int mi = 0; mi < 2; mi++) {
            int r0 = wm * 32 + mi * 16 + g;
            a[mi][0] = Qs32[r0 * 36 + ks2 + tig];
            a[mi][1] = Qs32[(r0 + 8) * 36 + ks2 + tig];
            a[mi][2] = Qs32[r0 * 36 + ks2 + tig + 4];
            a[mi][3] = Qs32[(r0 + 8) * 36 + ks2 + tig + 4];
        }
        #pragma unroll
        for (int ni = 0; ni < 8; ni++) {
            int n = wn * 64 + ni * 8 + g;
            u32 b0 = Ks32[n * 36 + ks2 + tig];
            u32 b1 = Ks32[n * 36 + ks2 + tig + 4];
            mma16816(acc[0][ni], a[0], b0, b1);
            mma16816(acc[1][ni], a[1], b0, b1);
        }
    }

    const int nl = wn * 64 + 2 * tig;
    float mv0[8], mv1[8];
    #pragma unroll
    for (int ni = 0; ni < 8; ni++) {
        mv0[ni] = mvs[nl + ni * 8];
        mv1[ni] = mvs[nl + ni * 8 + 1];
    }
    #pragma unroll
    for (int mi = 0; mi < 2; mi++) {
        #pragma unroll
        for (int rs = 0; rs < 2; rs++) {
            int m = tile_m * 128 + wm * 32 + mi * 16 + g + rs * 8;
            size_t rowoff = outbase + (size_t)m * TT;
            #pragma unroll
            for (int ni = 0; ni < 8; ni++) {
                int n = tile_n * 128 + nl + ni * 8;
                float v0 = acc[mi][ni][rs * 2 + 0] * mv0[ni]
                           - (1.0f - mv0[ni]) * NEGV;
                float v1 = acc[mi][ni][rs * 2 + 1] * mv1[ni]
                           - (1.0f - mv1[ni]) * NEGV;
                if (n < m)     v0 -= NEGV;
                if (n + 1 < m) v1 -= NEGV;
                *reinterpret_cast<float2*>(&out[rowoff + n]) =
                    make_float2(v0 * 0.125f, v1 * 0.125f);
            }
        }
    }
}

// ---------------------------------------------------------------------------
// Kernel 3: strict-lower fill.
// ---------------------------------------------------------------------------
__global__ void __launch_bounds__(256)
fill_kernel(const int* __restrict__ mask, float* __restrict__ out) {
    int idx = blockIdx.x;
    int tm = 1, rem = idx;
    while (rem >= tm) { rem -= tm; tm++; }
    const int tile_m = tm, tile_n = rem;

    const int bh  = blockIdx.y;
    const int b   = bh / HEADS;
    const int tid = threadIdx.x;
    const size_t outbase = (size_t)bh * TT * TT;

    __shared__ float colval[128];
    if (tid < 128) {
        float mv = (float)mask[b * TT + tile_n * 128 + tid];
        colval[tid] = (-(1.0f - mv) * NEGV - NEGV) * 0.125f;
    }
    __syncthreads();

    #pragma unroll
    for (int l = 0; l < 16; l++) {
        int f   = tid + l * 256;
        int row = f >> 5;
        int c4  = (f & 31) * 4;
        float4 v = *reinterpret_cast<const float4*>(&colval[c4]);
        int m = tile_m * 128 + row;
        int n = tile_n * 128 + c4;
        *reinterpret_cast<float4*>(&out[outbase + (size_t)m * TT + n]) = v;
    }
}

// ---------------------------------------------------------------------------
extern "C" void kernel_launch(void* const* d_in, const int* in_sizes, int n_in,
                              void* d_out, int out_size) {
    const float* hs   = (const float*)d_in[0];
    const int*   mask = (const int*)  d_in[1];
    const float* W    = (const float*)d_in[2];
    const float* bias = (const float*)d_in[3];
    float* out = (float*)d_out;

    const int proj_smem = NSTAGE * STAGE_BYTES;   // 81920
    cudaFuncSetAttribute(proj_rope_kernel,
                         cudaFuncAttributeMaxDynamicSharedMemorySize, proj_smem);

    prep_kernel<<<HS_BLOCKS + W_BLOCKS + ROPE_BLOCKS, 256>>>(hs, W);

    dim3 gA(NPROJ / 128, (BB * TT) / 128);   // (12, 64)
    proj_rope_kernel<<<gA, 512, proj_smem>>>(bias);

    dim3 gB(36, BB * HEADS);                 // upper tiles
    logits_kernel<<<gB, 256>>>(mask, out);

    dim3 gC(28, BB * HEADS);                 // strict-lower tiles
    fill_kernel<<<gC, 256>>>(mask, out);
}

// round 9
// speedup vs baseline: 1.5400x; 1.0328x over previous
#include <cuda_runtime.h>
#include <cuda_bf16.h>
#include <cstdint>
#include <math.h>

using u32 = unsigned int;

#define HEADS 12
#define DIM   64
#define BB    8
#define TT    1024
#define DIN   768
#define NPROJ 1536
#define NEGV  1000000000000.0f

// Scratch (no cudaMalloc allowed)
__device__ __nv_bfloat16 g_hs[BB*TT*DIN];        // hidden_states bf16 [m][k]
__device__ __nv_bfloat16 g_wT[NPROJ*DIN];        // W transposed bf16 [n][k]
__device__ __nv_bfloat16 g_q[BB*HEADS*TT*DIM];   // [bh][t][d]
__device__ __nv_bfloat16 g_k[BB*HEADS*TT*DIM];
__device__ float g_sin[32*TT];                   // transposed: [i][t]
__device__ float g_cos[32*TT];

// ---------------------------------------------------------------------------
__device__ __forceinline__ u32 smem_u32(const void* p) {
    u32 a;
    asm("{ .reg .u64 t; cvta.to.shared.u64 t, %1; cvt.u32.u64 %0, t; }"
        : "=r"(a) : "l"(p));
    return a;
}
__device__ __forceinline__ void cp_async16(u32 dst, const void* src) {
    asm volatile("cp.async.cg.shared.global [%0], [%1], 16;\n"
                 :: "r"(dst), "l"(src));
}
__device__ __forceinline__ void cp_commit() {
    asm volatile("cp.async.commit_group;\n" ::: "memory");
}
#define CP_WAIT(N) asm volatile("cp.async.wait_group %0;\n"::"n"(N):"memory")

__device__ __forceinline__ void mma16816(float d[4], const u32 a[4],
                                         const u32 b0, const u32 b1) {
    asm volatile(
        "mma.sync.aligned.m16n8k16.row.col.f32.bf16.bf16.f32 "
        "{%0,%1,%2,%3}, {%4,%5,%6,%7}, {%8,%9}, {%0,%1,%2,%3};\n"
        : "+f"(d[0]), "+f"(d[1]), "+f"(d[2]), "+f"(d[3])
        : "r"(a[0]), "r"(a[1]), "r"(a[2]), "r"(a[3]), "r"(b0), "r"(b1));
}

// ---------------------------------------------------------------------------
// Kernel 0: fused prep — conv_hs, conv_w transpose, rope table.
// ---------------------------------------------------------------------------
#define HS_BLOCKS   6144    // (BB*TT*DIN/4)/256
#define W_BLOCKS    1152    // (NPROJ/32)*(DIN/32)
#define ROPE_BLOCKS 128     // 32768/256

__global__ void __launch_bounds__(256)
prep_kernel(const float* __restrict__ hs, const float* __restrict__ W) {
    __shared__ float tile[32][33];
    const int blk = blockIdx.x;
    const int tid = threadIdx.x;

    if (blk < HS_BLOCKS) {
        int f = blk * 256 + tid;
        float4 v = reinterpret_cast<const float4*>(hs)[f];
        __nv_bfloat162 lo = __floats2bfloat162_rn(v.x, v.y);
        __nv_bfloat162 hi = __floats2bfloat162_rn(v.z, v.w);
        uint2 o;
        o.x = *reinterpret_cast<u32*>(&lo);
        o.y = *reinterpret_cast<u32*>(&hi);
        reinterpret_cast<uint2*>(g_hs)[f] = o;
    } else if (blk < HS_BLOCKS + W_BLOCKS) {
        int idx = blk - HS_BLOCKS;
        int n0 = (idx % 48) * 32, k0 = (idx / 48) * 32;
        int tx = tid & 31, ty = tid >> 5;
        #pragma unroll
        for (int r = ty; r < 32; r += 8)
            tile[r][tx] = W[(size_t)(k0 + r) * NPROJ + n0 + tx];
        __syncthreads();
        #pragma unroll
        for (int r = ty; r < 32; r += 8)
            g_wT[(size_t)(n0 + r) * DIN + k0 + tx] =
                __float2bfloat16(tile[tx][r]);
    } else {
        int id = (blk - HS_BLOCKS - W_BLOCKS) * 256 + tid;
        int t = id >> 5;
        int i = id & 31;
        float invf = exp2f(-(float)i * 0.4152410118610286f); // log2(1e4)/32
        float ang = (float)t * invf;
        float s, c;
        sincosf(ang, &s, &c);
        g_sin[i * TT + t] = s;
        g_cos[i * TT + t] = c;
    }
}

// ---------------------------------------------------------------------------
// Kernel 1: heterogeneous — projection GEMM CTAs interleaved 4:7 with
// strict-lower fill CTAs (fill has no dependency on proj; it rides the idle
// DRAM pipe while proj occupies tensor/smem).
// proj: block tile 128x128, BK=32, 16 warps (4m x 4n), 4-stage cp.async.
// fill: 512 threads fill two 128x128 output tiles with constant columns.
// ---------------------------------------------------------------------------
#define STAGE_BYTES (2 * 128 * 40 * 2)   // A + B, 20480 B
#define NSTAGE 4
#define PROJ_CTAS 768
#define FILL_CTAS 1344                    // 2688 tile-units / 2

__global__ void __launch_bounds__(512, 2)
proj_fill_kernel(const float* __restrict__ bias,
                 const int* __restrict__ mask,
                 float* __restrict__ out) {
    extern __shared__ char dsm[];
    const int L = blockIdx.x;
    const int grp = L / 11, off = L % 11;
    const int tid = threadIdx.x;

    if (off >= 4) {
        // ---------------- fill branch: two 128x128 tiles ----------------
        float* colval = reinterpret_cast<float*>(dsm);   // [2][128]
        const int fidx = grp * 7 + (off - 4);            // 0..1343
        const int half = tid >> 8;                       // 0..1
        const int ltid = tid & 255;
        const int unit = fidx * 2 + half;                // 0..2687
        const int bh   = unit % 96;
        const int b    = bh / HEADS;
        int tm = 1, rem = unit / 96;                     // tile idx 0..27
        while (rem >= tm) { rem -= tm; tm++; }
        const int tile_m = tm, tile_n = rem;
        const size_t outbase = (size_t)bh * TT * TT;

        if (ltid < 128) {
            float mv = (float)mask[b * TT + tile_n * 128 + ltid];
            colval[half * 128 + ltid] =
                (-(1.0f - mv) * NEGV - NEGV) * 0.125f;
        }
        __syncthreads();

        #pragma unroll
        for (int l = 0; l < 16; l++) {
            int f   = ltid + l * 256;       // 0..4095 float4 tasks
            int row = f >> 5;
            int c4  = (f & 31) * 4;
            float4 v = *reinterpret_cast<const float4*>(
                &colval[half * 128 + c4]);
            int m = tile_m * 128 + row;
            int n = tile_n * 128 + c4;
            *reinterpret_cast<float4*>(&out[outbase + (size_t)m * TT + n]) = v;
        }
        return;
    }

    // ---------------- proj branch ----------------
    const u32 sb = smem_u32(dsm);
    const int pidx = grp * 4 + off;                      // 0..767
    const int m0 = (pidx / 12) * 128;
    const int n0 = (pidx % 12) * 128;
    const int warp = tid >> 5, lane = tid & 31;
    const int wm = warp >> 2, wn = warp & 3;
    const int g = lane >> 2, tig = lane & 3;

    const int r_row = tid >> 2;            // 0..127
    const int r_kc  = (tid & 3) * 8;       // bf16 offset in 32-wide k chunk

    auto load_stage = [&](int k0c, int s) {
        u32 abase = sb + s * STAGE_BYTES;
        u32 bbase = abase + 128 * 80;
        cp_async16(abase + r_row * 80 + r_kc * 2,
                   g_hs + (size_t)(m0 + r_row) * DIN + k0c + r_kc);
        cp_async16(bbase + r_row * 80 + r_kc * 2,
                   g_wT + (size_t)(n0 + r_row) * DIN + k0c + r_kc);
        cp_commit();
    };

    float acc[2][4][4] = {};

    load_stage(0, 0);
    load_stage(32, 1);
    load_stage(64, 2);

    #pragma unroll 1
    for (int kt = 0; kt < 24; kt++) {
        CP_WAIT(2);
        __syncthreads();
        if (kt + 3 < 24) load_stage((kt + 3) * 32, (kt + 3) & 3);
        else             cp_commit();

        const int s = kt & 3;
        const u32* As32 = reinterpret_cast<const u32*>(dsm + s * STAGE_BYTES);
        const u32* Bs32 = As32 + (128 * 80 / 4);

        #pragma unroll
        for (int ks2 = 0; ks2 < 16; ks2 += 8) {
            u32 a[2][4];
            #pragma unroll
            for (int mi = 0; mi < 2; mi++) {
                int r0 = wm * 32 + mi * 16 + g;
                a[mi][0] = As32[r0 * 20 + ks2 + tig];
                a[mi][1] = As32[(r0 + 8) * 20 + ks2 + tig];
                a[mi][2] = As32[r0 * 20 + ks2 + tig + 4];
                a[mi][3] = As32[(r0 + 8) * 20 + ks2 + tig + 4];
            }
            #pragma unroll
            for (int ni = 0; ni < 4; ni++) {
                int n = wn * 32 + ni * 8 + g;
                u32 b0 = Bs32[n * 20 + ks2 + tig];
                u32 b1 = Bs32[n * 20 + ks2 + tig + 4];
                mma16816(acc[0][ni], a[0], b0, b1);
                mma16816(acc[1][ni], a[1], b0, b1);
            }
        }
    }

    #pragma unroll
    for (int ni = 0; ni < 4; ni++) {
        int n = n0 + wn * 32 + ni * 8 + 2 * tig;     // even column
        float b0v = __ldg(&bias[n]);
        float b1v = __ldg(&bias[n + 1]);
        int h = n >> 7, c = n & 127;
        bool isk = (c >= 64);
        int dd = isk ? c - 64 : c;
        int ip = dd >> 1;
        __nv_bfloat16* dst = isk ? g_k : g_q;
        #pragma unroll
        for (int mi = 0; mi < 2; mi++) {
            #pragma unroll
            for (int rs = 0; rs < 2; rs++) {
                int m = m0 + wm * 32 + mi * 16 + g + rs * 8;
                int t = m & (TT - 1);
                int batch = m >> 10;
                float s  = g_sin[ip * TT + t];
                float co = g_cos[ip * TT + t];
                float x0 = acc[mi][ni][rs * 2 + 0] + b0v;
                float x1 = acc[mi][ni][rs * 2 + 1] + b1v;
                size_t offb =
                    ((size_t)((batch * HEADS + h) * TT + t)) * DIM + dd;
                *reinterpret_cast<__nv_bfloat162*>(&dst[offb]) =
                    __floats2bfloat162_rn(x0 * co - x1 * s, x1 * co + x0 * s);
            }
        }
    }
}

// ---------------------------------------------------------------------------
// Kernel 2: logits — upper-triangular 128x128 tiles (36/bh). R3 form.
// ---------------------------------------------------------------------------
__global__ void __launch_bounds__(256)
logits_kernel(const int* __restrict__ mask, float* __restrict__ out) {
    int idx = blockIdx.x;
    int tm = 0, rem = idx;
    while (rem >= 8 - tm) { rem -= 8 - tm; tm++; }
    const int tile_m = tm, tile_n = tm + rem;

    const int bh  = blockIdx.y;
    const int b   = bh / HEADS;
    const int tid = threadIdx.x;
    const size_t outbase = (size_t)bh * TT * TT;

    __shared__ __nv_bfloat16 Qs[128 * 72];
    __shared__ __nv_bfloat16 Ks[128 * 72];
    __shared__ float mvs[128];
    u32* Qs32 = reinterpret_cast<u32*>(Qs);
    u32* Ks32 = reinterpret_cast<u32*>(Ks);

    const __nv_bfloat16* qptr = g_q + (size_t)bh * TT * DIM +
                                (size_t)tile_m * 128 * DIM;
    const __nv_bfloat16* kptr = g_k + (size_t)bh * TT * DIM +
                                (size_t)tile_n * 128 * DIM;

    if (tid < 128) mvs[tid] = (float)mask[b * TT + tile_n * 128 + tid];

    #pragma unroll
    for (int l = 0; l < 4; l++) {
        int f   = tid + l * 256;
        int row = f >> 3;
        int qo  = (f & 7) * 8;
        *reinterpret_cast<uint4*>(&Qs[row * 72 + qo]) =
            *reinterpret_cast<const uint4*>(&qptr[row * DIM + qo]);
        *reinterpret_cast<uint4*>(&Ks[row * 72 + qo]) =
            *reinterpret_cast<const uint4*>(&kptr[row * DIM + qo]);
    }
    __syncthreads();

    const int warp = tid >> 5, lane = tid & 31;
    const int wm = warp >> 1, wn = warp & 1;
    const int g = lane >> 2, tig = lane & 3;

    float acc[2][8][4] = {};
    #pragma unroll
    for (int ks2 = 0; ks2 < 32; ks2 += 8) {
        u32 a[2][4];
        #pragma unroll
        for (int mi = 0; mi < 2; mi++) {
            int r0 = wm * 32 + mi * 16 + g;
            a[mi][0] = Qs32[r0 * 36 + ks2 + tig];
            a[mi][1] = Qs32[(r0 + 8) * 36 + ks2 + tig];
            a[mi][2] = Qs32[r0 * 36 + ks2 + tig + 4];
            a[mi][3] = Qs32[(r0 + 8) * 36 + ks2 + tig + 4];
        }
        #pragma unroll
        for (int ni = 0; ni < 8; ni++) {
            int n = wn * 64 + ni * 8 + g;
            u32 b0 = Ks32[n * 36 + ks2 + tig];
            u32 b1 = Ks32[n * 36 + ks2 + tig + 4];
            mma16816(acc[0][ni], a[0], b0, b1);
            mma16816(acc[1][ni], a[1], b0, b1);
        }
    }

    const int nl = wn * 64 + 2 * tig;
    float mv0[8], mv1[8];
    #pragma unroll
    for (int ni = 0; ni < 8; ni++) {
        mv0[ni] = mvs[nl + ni * 8];
        mv1[ni] = mvs[nl + ni * 8 + 1];
    }
    #pragma unroll
    for (int mi = 0; mi < 2; mi++) {
        #pragma unroll
        for (int rs = 0; rs < 2; rs++) {
            int m = tile_m * 128 + wm * 32 + mi * 16 + g + rs * 8;
            size_t rowoff = outbase + (size_t)m * TT;
            #pragma unroll
            for (int ni = 0; ni < 8; ni++) {
                int n = tile_n * 128 + nl + ni * 8;
                float v0 = acc[mi][ni][rs * 2 + 0] * mv0[ni]
                           - (1.0f - mv0[ni]) * NEGV;
                float v1 = acc[mi][ni][rs * 2 + 1] * mv1[ni]
                           - (1.0f - mv1[ni]) * NEGV;
                if (n < m)     v0 -= NEGV;
                if (n + 1 < m) v1 -= NEGV;
                *reinterpret_cast<float2*>(&out[rowoff + n]) =
                    make_float2(v0 * 0.125f, v1 * 0.125f);
            }
        }
    }
}

// ---------------------------------------------------------------------------
extern "C" void kernel_launch(void* const* d_in, const int* in_sizes, int n_in,
                              void* d_out, int out_size) {
    const float* hs   = (const float*)d_in[0];
    const int*   mask = (const int*)  d_in[1];
    const float* W    = (const float*)d_in[2];
    const float* bias = (const float*)d_in[3];
    float* out = (float*)d_out;

    const int proj_smem = NSTAGE * STAGE_BYTES;   // 81920
    cudaFuncSetAttribute(proj_fill_kernel,
                         cudaFuncAttributeMaxDynamicSharedMemorySize, proj_smem);

    prep_kernel<<<HS_BLOCKS + W_BLOCKS + ROPE_BLOCKS, 256>>>(hs, W);

    proj_fill_kernel<<<2112, 512, proj_smem>>>(bias, mask, out);

    dim3 gB(36, BB * HEADS);                 // upper tiles
    logits_kernel<<<gB, 256>>>(mask, out);
}